// round 4
// baseline (speedup 1.0000x reference)
#include <cuda_runtime.h>
#include <math.h>

#define N_Q 6
#define NSTATE 64
#define SEQ 512
#define BATCH 256
#define BT (BATCH * SEQ)
#define PI_F 3.14159265358979323846f

typedef unsigned long long ull;

// ---------------- device-global precomputed tables ----------------
__device__ ulonglong2 g_UA[16 * 128];   // packed U rows for output kp   : {(ux,ux),(-uy,uy)}
__device__ ulonglong2 g_UB[16 * 128];   // packed U rows for output kp+32
__device__ float  g_A[NSTATE * N_Q];    // QSVT phase coefficients per (index, qubit)
__device__ int    g_src[NSTATE];        // QSVT source permutation
__device__ float  g_Mdt[36];            // Wdt @ Wx[0:3]  (6x6)
__device__ float  g_Mcw[108];           // Wc  @ Wx[9:15] (18x6)

// ---------------- per-(b,t) precomputed streams ----------------
__device__ float2 g_phase[(size_t)BT * 64];  // e^{-i theta_j}  (cos, -sin)   64 MB
__device__ float  g_psc[(size_t)BT * 12];    // cos(x*dt)[6], sin(x*dt)[6]
__device__ float  g_cw[(size_t)BT * 18];     // Mcw @ ang
__device__ float  g_d18[(size_t)BT * 18];    // D * ang

__device__ __forceinline__ float2 cmulf(float2 a, float2 b) {
    return make_float2(a.x * b.x - a.y * b.y, a.x * b.y + a.y * b.x);
}
__device__ __forceinline__ float2 caddf(float2 a, float2 b) {
    return make_float2(a.x + b.x, a.y + b.y);
}
__device__ __forceinline__ ull packf2(float lo, float hi) {
    return (ull)__float_as_uint(lo) | ((ull)__float_as_uint(hi) << 32);
}
__device__ __forceinline__ ull ffma2(ull a, ull b, ull c) {
    ull d;
    asm("fma.rn.f32x2 %0, %1, %2, %3;" : "=l"(d) : "l"(a), "l"(b), "l"(c));
    return d;
}
__device__ __forceinline__ ull fadd2(ull a, ull b) {
    ull d;
    asm("add.rn.f32x2 %0, %1, %2;" : "=l"(d) : "l"(a), "l"(b));
    return d;
}
__device__ __forceinline__ void barhalf(int id) {
    asm volatile("bar.sync %0, %1;" :: "r"(id), "r"(128) : "memory");
}

// ---------------- setup kernel: build packed U, QSVT tables, folded matrices ----------------
__global__ void qm_setup(const float* __restrict__ Wx,      // (15,6)
                         const float* __restrict__ Wdt,     // (6,3)
                         const float* __restrict__ poly,    // (4)
                         const float* __restrict__ qsvt,    // (18)
                         const float* __restrict__ cp,      // (60)
                         const float* __restrict__ Wc)      // (18,6)
{
    __shared__ float2 M[NSTATE][NSTATE];   // 32 KB ansatz matrix accumulator
    const int tid = threadIdx.x;           // 128 threads

    if (tid < 36) {
        int w = tid / 6, v = tid % 6;
        float acc = 0.f;
        for (int r = 0; r < 3; r++) acc = fmaf(Wdt[w * 3 + r], Wx[r * 6 + v], acc);
        g_Mdt[tid] = acc;
    }
    if (tid < 108) {
        int j = tid / 6, v = tid % 6;
        float acc = 0.f;
        for (int w = 0; w < 6; w++) acc = fmaf(Wc[j * 6 + w], Wx[(9 + w) * 6 + v], acc);
        g_Mcw[tid] = acc;
    }
    if (tid < NSTATE) {
        const int chc[11] = {0, 1, 2, 3, 4, 5, 5, 4, 3, 2, 1};
        const int cht[11] = {1, 2, 3, 4, 5, 0, 4, 3, 2, 1, 0};
        int k = tid;
        float A[N_Q] = {0.f, 0.f, 0.f, 0.f, 0.f, 0.f};
        for (int deg = 3; deg >= 0; --deg) {
            for (int ci = 10; ci >= 0; --ci) {
                int c = chc[ci], t = cht[ci];
                k ^= ((k >> (5 - c)) & 1) << (5 - t);
            }
            float coeff = poly[deg];
            for (int w = 0; w < N_Q; w++) {
                float wgt = (deg < 3) ? qsvt[deg * 6 + w] : 1.0f;
                float b = (float)((k >> (5 - w)) & 1);
                A[w] += 0.5f * (1.0f - 2.0f * b) * coeff * wgt * PI_F;
            }
        }
        g_src[tid] = k;
        for (int w = 0; w < N_Q; w++) g_A[tid * N_Q + w] = A[w];
    }

    for (int i = tid; i < NSTATE * NSTATE; i += 128) {
        int r = i >> 6, c = i & 63;
        M[r][c] = make_float2(r == c ? 1.f : 0.f, 0.f);
    }
    __syncthreads();

    auto apply1 = [&](int tq, float2 g00, float2 g01, float2 g10, float2 g11, int ctrl) {
        int m = 1 << (5 - tq);
        for (int idx = tid; idx < 32 * 64; idx += 128) {
            int col = idx & 63, pr = idx >> 6;
            int low = pr & (m - 1);
            int k0 = ((pr & ~(m - 1)) << 1) | low;
            int k1 = k0 | m;
            if (ctrl >= 0 && !((k0 >> (5 - ctrl)) & 1)) continue;
            float2 a0 = M[k0][col], a1 = M[k1][col];
            M[k0][col] = caddf(cmulf(g00, a0), cmulf(g01, a1));
            M[k1][col] = caddf(cmulf(g10, a0), cmulf(g11, a1));
        }
        __syncthreads();
    };

    int p = 0;
    for (int layer = 0; layer < 2; ++layer) {
        for (int i = 0; i < N_Q; i++) {
            float thx = cp[p], thy = cp[p + 1], thz = cp[p + 2];
            p += 3;
            float c, s;
            c = cosf(0.5f * thx); s = sinf(0.5f * thx);
            apply1(i, make_float2(c, 0), make_float2(0, -s), make_float2(0, -s), make_float2(c, 0), -1);
            c = cosf(0.5f * thy); s = sinf(0.5f * thy);
            apply1(i, make_float2(c, 0), make_float2(-s, 0), make_float2(s, 0), make_float2(c, 0), -1);
            c = cosf(0.5f * thz); s = sinf(0.5f * thz);
            apply1(i, make_float2(c, -s), make_float2(0, 0), make_float2(0, 0), make_float2(c, s), -1);
        }
        for (int i = 0; i < N_Q; i++) {
            float th = cp[p++];
            float c = cosf(0.5f * th), s = sinf(0.5f * th);
            apply1((i + 1) % N_Q, make_float2(c, 0), make_float2(0, -s), make_float2(0, -s), make_float2(c, 0), i);
        }
        for (int i = N_Q - 1; i >= 0; i--) {
            float th = cp[p++];
            float c = cosf(0.5f * th), s = sinf(0.5f * th);
            apply1((i + 5) % N_Q, make_float2(c, 0), make_float2(0, -s), make_float2(0, -s), make_float2(c, 0), i);
        }
    }

    // pack U for the FFMA2 register layout of qm_main:
    // thread tidb: kp = tidb>>2, q = tidb&3; outputs (kp, kp+32); j = q*16 + jj
    {
        int kp = tid >> 2, q = tid & 3;
        for (int jj = 0; jj < 16; jj++) {
            int j = q * 16 + jj;
            float2 a = M[kp][j];
            float2 b = M[kp + 32][j];
            g_UA[jj * 128 + tid] = make_ulonglong2(packf2(a.x, a.x), packf2(-a.y, a.y));
            g_UB[jj * 128 + tid] = make_ulonglong2(packf2(b.x, b.x), packf2(-b.y, b.y));
        }
    }
}

// ---------------- precompute kernel: one warp per (b,t) ----------------
__global__ void __launch_bounds__(256) qm_pre(const float* __restrict__ angles,
                                              const float* __restrict__ bdt,
                                              const float* __restrict__ D)
{
    const int wid  = (blockIdx.x * blockDim.x + threadIdx.x) >> 5;
    const int lane = threadIdx.x & 31;
    if (wid >= BT) return;

    const float* ang = angles + (size_t)wid * 6;
    float al = (lane < 6) ? ang[lane] : 0.f;
    float angv[6];
#pragma unroll
    for (int w = 0; w < 6; w++) angv[w] = __shfl_sync(0xffffffffu, al, w);

    float dtl = 0.f;
    if (lane < 6) {
        float x = bdt[lane];
#pragma unroll
        for (int v = 0; v < 6; v++) x = fmaf(g_Mdt[lane * 6 + v], angv[v], x);
        // tanh(softplus(x)) = 1 - 2/(E^2 + 2E + 2),  E = e^x   (clamped; exact to fp32 beyond 15)
        x = fminf(x, 15.f);
        float E = __expf(x);
        float den = fmaf(E, E + 2.f, 2.f);
        dtl = (1.f - __fdividef(2.f, den)) * PI_F;
    }
    float dtv[6];
#pragma unroll
    for (int w = 0; w < 6; w++) dtv[w] = __shfl_sync(0xffffffffu, dtl, w);

    if (lane < 6) {
        float sv, cv;
        __sincosf(al * dtl, &sv, &cv);
        g_psc[(size_t)wid * 12 + lane]     = cv;
        g_psc[(size_t)wid * 12 + 6 + lane] = sv;
    }
#pragma unroll
    for (int rep = 0; rep < 2; rep++) {
        int j = lane + rep * 32;
        float th = 0.f;
#pragma unroll
        for (int w = 0; w < 6; w++) th = fmaf(g_A[j * 6 + w], dtv[w], th);
        float sn, cs;
        __sincosf(th, &sn, &cs);
        g_phase[(size_t)wid * 64 + j] = make_float2(cs, -sn);
    }
    if (lane < 18) {
        float cw = 0.f;
#pragma unroll
        for (int v = 0; v < 6; v++) cw = fmaf(g_Mcw[lane * 6 + v], angv[v], cw);
        g_cw[(size_t)wid * 18 + lane]  = cw;
        g_d18[(size_t)wid * 18 + lane] = D[lane] * angv[lane % 6];
    }
}

// ---------------- main kernel: 2 batch elements per CTA, named-barrier halves ----------------
__global__ void __launch_bounds__(256, 1) qm_main(float* __restrict__ out)
{
    __shared__ float2 s_sh[2][64];   // (sx, sy)
    __shared__ float2 w_sh[2][64];   // (sy, sx)
    __shared__ float2 a_sh[2][64];
    __shared__ float  hc_sh[2][6], hs_sh[2][6];

    const int tid   = threadIdx.x;
    const int half  = tid >> 7;
    const int tidb  = tid & 127;
    const int b     = blockIdx.x * 2 + half;
    const int barid = 1 + half;
    const int kp = tidb >> 2, q = tidb & 3;

    // U in registers, packed for FFMA2
    ulonglong2 uA[16], uB[16];
#pragma unroll
    for (int jj = 0; jj < 16; jj++) { uA[jj] = g_UA[jj * 128 + tidb]; uB[jj] = g_UB[jj * 128 + tidb]; }

    const int srcj = g_src[tidb & 63];

    if (tidb < 6) { hc_sh[half][tidb] = 1.f; hs_sh[half][tidb] = 0.f; }

    const size_t bt0 = (size_t)b * SEQ;
    float2 phv = make_float2(0.f, 0.f);
    if (tidb < 64) phv = g_phase[bt0 * 64 + tidb];

    const int wg = tidb >> 3, rg = tidb & 7;
    const bool lead = (tidb < 48) && (rg == 0);
    float pcv = 0, psv = 0, c0 = 0, c1 = 0, c2 = 0, e0 = 0, e1 = 0, e2 = 0;
    if (lead) {
        const float* P = g_psc + bt0 * 12;
        pcv = P[wg]; psv = P[6 + wg];
        const float* C = g_cw + bt0 * 18;
        c0 = C[wg]; c1 = C[6 + wg]; c2 = C[12 + wg];
        const float* E = g_d18 + bt0 * 18;
        e0 = E[wg]; e1 = E[6 + wg]; e2 = E[12 + wg];
    }
    __syncthreads();

    for (int t = 0; t < SEQ; ++t) {
        const size_t btn = bt0 + ((t + 1 < SEQ) ? t + 1 : t);

        // ---- Phase B: s_j = r[src[j]] * phase_j ; prefetch next phase ----
        float2 phn = phv;
        if (tidb < 64) {
            float rr = 1.f;
#pragma unroll
            for (int w6 = 0; w6 < 6; w6++) {
                float hv = ((srcj >> (5 - w6)) & 1) ? hs_sh[half][w6] : hc_sh[half][w6];
                rr *= hv;
            }
            float sx = rr * phv.x, sy = rr * phv.y;
            s_sh[half][tidb] = make_float2(sx, sy);
            w_sh[half][tidb] = make_float2(sy, sx);
            phn = g_phase[btn * 64 + tidb];
        }
        float pcn = pcv, psn = psv, c0n = c0, c1n = c1, c2n = c2, e0n = e0, e1n = e1, e2n = e2;
        if (lead) {
            const float* P = g_psc + btn * 12;
            pcn = P[wg]; psn = P[6 + wg];
            const float* C = g_cw + btn * 18;
            c0n = C[wg]; c1n = C[6 + wg]; c2n = C[12 + wg];
            const float* E = g_d18 + btn * 18;
            e0n = E[wg]; e1n = E[6 + wg]; e2n = E[12 + wg];
        }
        barhalf(barid);

        // ---- Phase C: 64x64 complex matvec via packed FFMA2, 2 outputs/thread ----
        ull acc0 = 0ull, acc1 = 0ull;
        const ull* sp = reinterpret_cast<const ull*>(s_sh[half]);
        const ull* wp = reinterpret_cast<const ull*>(w_sh[half]);
#pragma unroll
        for (int jj = 0; jj < 16; jj++) {
            int j = q * 16 + jj;
            ull sv = sp[j], wv = wp[j];
            acc0 = ffma2(uA[jj].x, sv, acc0);
            acc0 = ffma2(uA[jj].y, wv, acc0);
            acc1 = ffma2(uB[jj].x, sv, acc1);
            acc1 = ffma2(uB[jj].y, wv, acc1);
        }
        acc0 = fadd2(acc0, __shfl_xor_sync(0xffffffffu, acc0, 1));
        acc0 = fadd2(acc0, __shfl_xor_sync(0xffffffffu, acc0, 2));
        acc1 = fadd2(acc1, __shfl_xor_sync(0xffffffffu, acc1, 1));
        acc1 = fadd2(acc1, __shfl_xor_sync(0xffffffffu, acc1, 2));
        if (q == 0) {
            a_sh[half][kp]      = make_float2(__uint_as_float((unsigned)acc0), __uint_as_float((unsigned)(acc0 >> 32)));
            a_sh[half][kp + 32] = make_float2(__uint_as_float((unsigned)acc1), __uint_as_float((unsigned)(acc1 >> 32)));
        }
        barhalf(barid);

        // ---- Phase D+E fused: measurement sums, epilogue, h sincos ----
        if (tidb < 48) {
            const int m = 1 << (5 - wg);
            float zp = 0.f, rp = 0.f, ip = 0.f;
#pragma unroll
            for (int pi = 0; pi < 4; pi++) {
                int p = rg * 4 + pi;
                int k = ((p & ~(m - 1)) << 1) | (p & (m - 1));
                float2 a  = a_sh[half][k];
                float2 pa = a_sh[half][k | m];
                zp += a.x * a.x + a.y * a.y - pa.x * pa.x - pa.y * pa.y;
                rp += a.x * pa.x + a.y * pa.y;
                ip += a.x * pa.y - a.y * pa.x;
            }
            unsigned gm = 0xFFu << ((wg * 8) & 31);
#pragma unroll
            for (int off = 1; off < 8; off <<= 1) {
                zp += __shfl_xor_sync(gm, zp, off);
                rp += __shfl_xor_sync(gm, rp, off);
                ip += __shfl_xor_sync(gm, ip, off);
            }
            if (rg == 0) {
                float mx = fmaf(psv, zp,  2.f * pcv * rp);
                float my = 2.f * ip;
                float mz = fmaf(pcv, zp, -2.f * psv * rp);
                float hs_, hc_;
                __sincosf(0.5f * mz, &hs_, &hc_);
                hc_sh[half][wg] = hc_;
                hs_sh[half][wg] = hs_;
                float* ob = out + (bt0 + t) * 18;
                ob[wg]      = fmaf(c0, mx, e0);
                ob[6 + wg]  = fmaf(c1, my, e1);
                ob[12 + wg] = fmaf(c2, mz, e2);
            }
        }
        barhalf(barid);

        phv = phn;
        pcv = pcn; psv = psn;
        c0 = c0n; c1 = c1n; c2 = c2n;
        e0 = e0n; e1 = e1n; e2 = e2n;
    }
}

extern "C" void kernel_launch(void* const* d_in, const int* in_sizes, int n_in,
                              void* d_out, int out_size)
{
    const float* angles = (const float*)d_in[0];   // (256,512,6)
    const float* Wx     = (const float*)d_in[1];   // (15,6)
    const float* Wdt    = (const float*)d_in[2];   // (6,3)
    const float* bdt    = (const float*)d_in[3];   // (6)
    const float* poly   = (const float*)d_in[4];   // (4)
    const float* qsvt   = (const float*)d_in[5];   // (18)
    const float* cp     = (const float*)d_in[6];   // (60)
    const float* D      = (const float*)d_in[7];   // (18)
    const float* Wc     = (const float*)d_in[8];   // (18,6)
    float* out = (float*)d_out;                    // (256,512,18)

    qm_setup<<<1, 128>>>(Wx, Wdt, poly, qsvt, cp, Wc);
    qm_pre<<<BT / 8, 256>>>(angles, bdt, D);       // 1 warp per (b,t)
    qm_main<<<BATCH / 2, 256>>>(out);
}

// round 6
// speedup vs baseline: 1.0317x; 1.0317x over previous
#include <cuda_runtime.h>
#include <math.h>

#define N_Q 6
#define NSTATE 64
#define SEQ 512
#define BATCH 256
#define PI_F 3.14159265358979323846f

typedef unsigned long long ull;

// ---------------- device-global precomputed tables ----------------
__device__ float2 g_UA[16 * 128];   // U[kp][q*16+jj] as {ux,uy}
__device__ float2 g_UB[16 * 128];   // U[kp+32][q*16+jj]
__device__ float  g_A[NSTATE * N_Q];
__device__ int    g_src[NSTATE];
__device__ float  g_Mdt[36];        // Wdt @ Wx[0:3]  (6x6)
__device__ float  g_Mcw[108];       // Wc  @ Wx[9:15] (18x6)

__device__ __forceinline__ float2 cmulf(float2 a, float2 b) {
    return make_float2(a.x * b.x - a.y * b.y, a.x * b.y + a.y * b.x);
}
__device__ __forceinline__ float2 caddf(float2 a, float2 b) {
    return make_float2(a.x + b.x, a.y + b.y);
}
__device__ __forceinline__ ull packf2(float lo, float hi) {
    return (ull)__float_as_uint(lo) | ((ull)__float_as_uint(hi) << 32);
}
__device__ __forceinline__ float f2lo(ull v) { return __uint_as_float((unsigned)v); }
__device__ __forceinline__ float f2hi(ull v) { return __uint_as_float((unsigned)(v >> 32)); }
__device__ __forceinline__ ull ffma2(ull a, ull b, ull c) {
    ull d;
    asm("fma.rn.f32x2 %0, %1, %2, %3;" : "=l"(d) : "l"(a), "l"(b), "l"(c));
    return d;
}
__device__ __forceinline__ ull fadd2(ull a, ull b) {
    ull d;
    asm("add.rn.f32x2 %0, %1, %2;" : "=l"(d) : "l"(a), "l"(b));
    return d;
}

// ---------------- setup kernel ----------------
__global__ void qm_setup(const float* __restrict__ Wx,      // (15,6)
                         const float* __restrict__ Wdt,     // (6,3)
                         const float* __restrict__ poly,    // (4)
                         const float* __restrict__ qsvt,    // (18)
                         const float* __restrict__ cp,      // (60)
                         const float* __restrict__ Wc)      // (18,6)
{
    __shared__ float2 M[NSTATE][NSTATE];
    const int tid = threadIdx.x;           // 256 threads
    const int nt  = blockDim.x;

    if (tid < 36) {
        int w = tid / 6, v = tid % 6;
        float acc = 0.f;
        for (int r = 0; r < 3; r++) acc = fmaf(Wdt[w * 3 + r], Wx[r * 6 + v], acc);
        g_Mdt[tid] = acc;
    }
    if (tid < 108) {
        int j = tid / 6, v = tid % 6;
        float acc = 0.f;
        for (int w = 0; w < 6; w++) acc = fmaf(Wc[j * 6 + w], Wx[(9 + w) * 6 + v], acc);
        g_Mcw[tid] = acc;
    }
    if (tid < NSTATE) {
        const int chc[11] = {0, 1, 2, 3, 4, 5, 5, 4, 3, 2, 1};
        const int cht[11] = {1, 2, 3, 4, 5, 0, 4, 3, 2, 1, 0};
        int k = tid;
        float A[N_Q] = {0.f, 0.f, 0.f, 0.f, 0.f, 0.f};
        for (int deg = 3; deg >= 0; --deg) {
            for (int ci = 10; ci >= 0; --ci) {
                int c = chc[ci], t = cht[ci];
                k ^= ((k >> (5 - c)) & 1) << (5 - t);
            }
            float coeff = poly[deg];
            for (int w = 0; w < N_Q; w++) {
                float wgt = (deg < 3) ? qsvt[deg * 6 + w] : 1.0f;
                float b = (float)((k >> (5 - w)) & 1);
                A[w] += 0.5f * (1.0f - 2.0f * b) * coeff * wgt * PI_F;
            }
        }
        g_src[tid] = k;
        for (int w = 0; w < N_Q; w++) g_A[tid * N_Q + w] = A[w];
    }

    for (int i = tid; i < NSTATE * NSTATE; i += nt) {
        int r = i >> 6, c = i & 63;
        M[r][c] = make_float2(r == c ? 1.f : 0.f, 0.f);
    }
    __syncthreads();

    auto apply1 = [&](int tq, float2 g00, float2 g01, float2 g10, float2 g11, int ctrl) {
        int m = 1 << (5 - tq);
        for (int idx = tid; idx < 32 * 64; idx += nt) {
            int col = idx & 63, pr = idx >> 6;
            int low = pr & (m - 1);
            int k0 = ((pr & ~(m - 1)) << 1) | low;
            int k1 = k0 | m;
            if (ctrl >= 0 && !((k0 >> (5 - ctrl)) & 1)) continue;
            float2 a0 = M[k0][col], a1 = M[k1][col];
            M[k0][col] = caddf(cmulf(g00, a0), cmulf(g01, a1));
            M[k1][col] = caddf(cmulf(g10, a0), cmulf(g11, a1));
        }
        __syncthreads();
    };

    int p = 0;
    for (int layer = 0; layer < 2; ++layer) {
        for (int i = 0; i < N_Q; i++) {
            float thx = cp[p], thy = cp[p + 1], thz = cp[p + 2];
            p += 3;
            float c, s;
            c = cosf(0.5f * thx); s = sinf(0.5f * thx);
            apply1(i, make_float2(c, 0), make_float2(0, -s), make_float2(0, -s), make_float2(c, 0), -1);
            c = cosf(0.5f * thy); s = sinf(0.5f * thy);
            apply1(i, make_float2(c, 0), make_float2(-s, 0), make_float2(s, 0), make_float2(c, 0), -1);
            c = cosf(0.5f * thz); s = sinf(0.5f * thz);
            apply1(i, make_float2(c, -s), make_float2(0, 0), make_float2(0, 0), make_float2(c, s), -1);
        }
        for (int i = 0; i < N_Q; i++) {
            float th = cp[p++];
            float c = cosf(0.5f * th), s = sinf(0.5f * th);
            apply1((i + 1) % N_Q, make_float2(c, 0), make_float2(0, -s), make_float2(0, -s), make_float2(c, 0), i);
        }
        for (int i = N_Q - 1; i >= 0; i--) {
            float th = cp[p++];
            float c = cosf(0.5f * th), s = sinf(0.5f * th);
            apply1((i + 5) % N_Q, make_float2(c, 0), make_float2(0, -s), make_float2(0, -s), make_float2(c, 0), i);
        }
    }

    if (tid < 128) {
        int kp = tid >> 2, q = tid & 3;
        for (int jj = 0; jj < 16; jj++) {
            int j = q * 16 + jj;
            g_UA[jj * 128 + tid] = M[kp][j];
            g_UB[jj * 128 + tid] = M[kp + 32][j];
        }
    }
}

// ---------------- main kernel: one CTA (128 thr) per batch, 3 barriers/step ----------------
__global__ void __launch_bounds__(128) qm_main(const float* __restrict__ angles,
                                               const float* __restrict__ bdt,
                                               const float* __restrict__ Dp,
                                               float* __restrict__ out)
{
    __shared__ float2 s_sh[64], w_sh[64], a_sh[64];
    __shared__ float  hsc[12];          // cos(h/2) [0..5], sin(h/2) [6..11]
    __shared__ float  dt_sh[2][6];
    __shared__ float  psc_sh[2][12];    // cos(x*dt) [0..5], sin [6..11]
    __shared__ float  ang_sh[2][6];
    __shared__ float  cw_sh[18], dd_sh[18];

    const int tid = threadIdx.x;
    const int b   = blockIdx.x;
    const int kp  = tid >> 2, q = tid & 3;
    const float* angp = angles + (size_t)b * SEQ * 6;

    // U rows in registers ({ux,uy} packed once)
    float2 uA[16], uB[16];
#pragma unroll
    for (int jj = 0; jj < 16; jj++) { uA[jj] = g_UA[jj * 128 + tid]; uB[jj] = g_UB[jj * 128 + tid]; }

    // Phase-B per-thread constants
    float Ac[6];
    int hidx[6];
    if (tid < 64) {
        int srcj = g_src[tid];
#pragma unroll
        for (int w = 0; w < 6; w++) {
            Ac[w] = g_A[tid * 6 + w];
            hidx[w] = w + 6 * ((srcj >> (5 - w)) & 1);
        }
    }

    // warp2 (tid 64..95): dt/psc producer constants + angle prefetch pipeline
    float Mdtv[6], bdtv = 0.f, angA = 0.f;
    // warp3 (tid 96..127): cw/d18 producer constants
    float Mcwv[6], Dv = 0.f;
    if (tid >= 64 && tid < 96) {
        int lane = tid - 64;
        if (lane < 6) {
            bdtv = bdt[lane];
#pragma unroll
            for (int v = 0; v < 6; v++) Mdtv[v] = g_Mdt[lane * 6 + v];
        }
    }
    if (tid >= 96) {
        int lane = tid - 96;
        if (lane < 18) {
            Dv = Dp[lane];
#pragma unroll
            for (int v = 0; v < 6; v++) Mcwv[v] = g_Mcw[lane * 6 + v];
        }
    }

    if (tid < 12) hsc[tid] = (tid < 6) ? 1.f : 0.f;

    // prologue: warp2 computes dt/psc/ang for t=0, prefetches ang(1)
    if (tid >= 64 && tid < 96) {
        int lane = tid - 64;
        float a0 = (lane < 6) ? angp[lane] : 0.f;
        float av[6];
#pragma unroll
        for (int v = 0; v < 6; v++) av[v] = __shfl_sync(0xffffffffu, a0, v);
        if (lane < 6) {
            ang_sh[0][lane] = a0;
            float x = bdtv;
#pragma unroll
            for (int v = 0; v < 6; v++) x = fmaf(Mdtv[v], av[v], x);
            x = fminf(x, 15.f);
            float E = __expf(x);
            float dt = (1.f - __fdividef(2.f, fmaf(E, E + 2.f, 2.f))) * PI_F;
            dt_sh[0][lane] = dt;
            float sv_, cv_;
            __sincosf(a0 * dt, &sv_, &cv_);
            psc_sh[0][lane] = cv_;
            psc_sh[0][6 + lane] = sv_;
            angA = angp[6 + lane];     // ang(1)
        }
    }
    __syncthreads();

    const int wg = tid >> 3, rg = tid & 7;

    for (int t = 0; t < SEQ; ++t) {
        const int p = t & 1, pn = p ^ 1;

        // ---- Phase B: build s (warps 0-1); produce next-step scalars (warps 2-3) ----
        if (tid < 64) {
            float th = 0.f;
#pragma unroll
            for (int w = 0; w < 6; w++) th = fmaf(Ac[w], dt_sh[p][w], th);
            float sn, cs;
            __sincosf(th, &sn, &cs);
            float r = hsc[hidx[0]];
#pragma unroll
            for (int w = 1; w < 6; w++) r *= hsc[hidx[w]];
            float sx = r * cs, sy = -r * sn;
            s_sh[tid] = make_float2(sx, sy);
            w_sh[tid] = make_float2(sy, sx);
        } else if (tid < 96) {
            // warp2: dt/psc for t+1, using angA = ang(t+1); prefetch ang(t+2)
            int lane = tid - 64;
            float an = angA;
            float av[6];
#pragma unroll
            for (int v = 0; v < 6; v++) av[v] = __shfl_sync(0xffffffffu, an, v);
            if (lane < 6) {
                ang_sh[pn][lane] = an;
                float x = bdtv;
#pragma unroll
                for (int v = 0; v < 6; v++) x = fmaf(Mdtv[v], av[v], x);
                x = fminf(x, 15.f);
                float E = __expf(x);
                float dt = (1.f - __fdividef(2.f, fmaf(E, E + 2.f, 2.f))) * PI_F;
                dt_sh[pn][lane] = dt;
                float sv_, cv_;
                __sincosf(an * dt, &sv_, &cv_);
                psc_sh[pn][lane] = cv_;
                psc_sh[pn][6 + lane] = sv_;
                int t2 = (t + 2 < SEQ) ? t + 2 : SEQ - 1;
                angA = angp[t2 * 6 + lane];
            }
        } else {
            // warp3: cw/d18 for step t, from ang_sh[p] (= ang(t))
            int lane = tid - 96;
            if (lane < 18) {
                float avv[6];
#pragma unroll
                for (int v = 0; v < 6; v++) avv[v] = ang_sh[p][v];
                float cw = 0.f;
#pragma unroll
                for (int v = 0; v < 6; v++) cw = fmaf(Mcwv[v], avv[v], cw);
                cw_sh[lane] = cw;
                dd_sh[lane] = Dv * avv[lane % 6];
            }
        }
        __syncthreads();

        // ---- Phase C: 64x64 complex matvec, FFMA2 P/Q form, 2 outputs/thread ----
        {
            ull PA = 0ull, QA = 0ull, PB = 0ull, QB = 0ull;
            const ull* sp = reinterpret_cast<const ull*>(s_sh);
            const ull* wp = reinterpret_cast<const ull*>(w_sh);
#pragma unroll
            for (int jj = 0; jj < 16; jj++) {
                int j = q * 16 + jj;
                ull sv = sp[j], wv = wp[j];
                ull ua = *reinterpret_cast<const ull*>(&uA[jj]);
                ull ub = *reinterpret_cast<const ull*>(&uB[jj]);
                PA = ffma2(ua, sv, PA);
                QA = ffma2(ua, wv, QA);
                PB = ffma2(ub, sv, PB);
                QB = ffma2(ub, wv, QB);
            }
            ull vA = packf2(f2lo(PA) - f2hi(PA), f2lo(QA) + f2hi(QA));
            ull vB = packf2(f2lo(PB) - f2hi(PB), f2lo(QB) + f2hi(QB));
            vA = fadd2(vA, __shfl_xor_sync(0xffffffffu, vA, 1));
            vA = fadd2(vA, __shfl_xor_sync(0xffffffffu, vA, 2));
            vB = fadd2(vB, __shfl_xor_sync(0xffffffffu, vB, 1));
            vB = fadd2(vB, __shfl_xor_sync(0xffffffffu, vB, 2));
            if (q == 0) {
                a_sh[kp]      = make_float2(f2lo(vA), f2hi(vA));
                a_sh[kp + 32] = make_float2(f2lo(vB), f2hi(vB));
            }
        }
        __syncthreads();

        // ---- Phase D+E: measurement sums, epilogue, h update ----
        if (tid < 48) {
            const int m = 1 << (5 - wg);
            float zp = 0.f, rp = 0.f, ip = 0.f;
#pragma unroll
            for (int pi = 0; pi < 4; pi++) {
                int pr = rg * 4 + pi;
                int k = ((pr & ~(m - 1)) << 1) | (pr & (m - 1));
                float2 a  = a_sh[k];
                float2 pa = a_sh[k | m];
                zp += a.x * a.x + a.y * a.y - pa.x * pa.x - pa.y * pa.y;
                rp += a.x * pa.x + a.y * pa.y;
                ip += a.x * pa.y - a.y * pa.x;
            }
            unsigned gm = 0xFFu << ((wg * 8) & 31);
#pragma unroll
            for (int off = 1; off < 8; off <<= 1) {
                zp += __shfl_xor_sync(gm, zp, off);
                rp += __shfl_xor_sync(gm, rp, off);
                ip += __shfl_xor_sync(gm, ip, off);
            }
            if (rg == 0) {
                float pcv = psc_sh[p][wg], psv = psc_sh[p][6 + wg];
                float mx = fmaf(psv, zp,  2.f * pcv * rp);
                float my = 2.f * ip;
                float mz = fmaf(pcv, zp, -2.f * psv * rp);
                float hs_, hc_;
                __sincosf(0.5f * mz, &hs_, &hc_);
                hsc[wg]     = hc_;
                hsc[6 + wg] = hs_;
                float* ob = out + ((size_t)b * SEQ + t) * 18;
                ob[wg]      = fmaf(cw_sh[wg],      mx, dd_sh[wg]);
                ob[6 + wg]  = fmaf(cw_sh[6 + wg],  my, dd_sh[6 + wg]);
                ob[12 + wg] = fmaf(cw_sh[12 + wg], mz, dd_sh[12 + wg]);
            }
        }
        __syncthreads();
    }
}

extern "C" void kernel_launch(void* const* d_in, const int* in_sizes, int n_in,
                              void* d_out, int out_size)
{
    const float* angles = (const float*)d_in[0];   // (256,512,6)
    const float* Wx     = (const float*)d_in[1];   // (15,6)
    const float* Wdt    = (const float*)d_in[2];   // (6,3)
    const float* bdt    = (const float*)d_in[3];   // (6)
    const float* poly   = (const float*)d_in[4];   // (4)
    const float* qsvt   = (const float*)d_in[5];   // (18)
    const float* cp     = (const float*)d_in[6];   // (60)
    const float* D      = (const float*)d_in[7];   // (18)
    const float* Wc     = (const float*)d_in[8];   // (18,6)
    float* out = (float*)d_out;                    // (256,512,18)

    qm_setup<<<1, 256>>>(Wx, Wdt, poly, qsvt, cp, Wc);
    qm_main<<<BATCH, 128>>>(angles, bdt, D, out);
}